// round 4
// baseline (speedup 1.0000x reference)
#include <cuda_runtime.h>

// Problem dims (fixed by the dataset; runtime values derived from in_sizes).
#define NMAX 50000
#define EMAX 800000

// ---- scratch (device globals; no allocation allowed) ----
__device__ float g_q[NMAX * 128];
__device__ float g_k[NMAX * 128];
__device__ float g_v[NMAX * 128];
__device__ float g_h1[NMAX * 32];   // layer-1 output accumulator (skip + attention)
__device__ float g_h2[NMAX * 32];   // layer-2 output accumulator
__device__ float g_expa[EMAX * 4];  // exp(alpha) per edge per head
__device__ float g_s[NMAX * 4];     // softmax denominators per node per head

// ---------------------------------------------------------------------------
// Zero the softmax denominator buffer.
// ---------------------------------------------------------------------------
__global__ void zero_s_kernel(int n) {
    int i = blockIdx.x * blockDim.x + threadIdx.x;
    if (i < n) g_s[i] = 0.0f;
}

// ---------------------------------------------------------------------------
// Node linears: q = x@Wq+bq, k = x@Wk+bk, v = x@Wv+bv  ([N,128] each)
// out = x@Ws+bs ([N,32]) -- the skip connection, becomes the accumulator.
// layer==0: read xin (raw). layer==1: read g_h1 with relu applied.
// One block per node, 128 threads (one per output column).
// ---------------------------------------------------------------------------
__global__ void node_linear_kernel(
    const float* __restrict__ xin, int layer,
    const float* __restrict__ Wq, const float* __restrict__ bq,
    const float* __restrict__ Wk, const float* __restrict__ bk,
    const float* __restrict__ Wv, const float* __restrict__ bv,
    const float* __restrict__ Ws, const float* __restrict__ bs,
    int N)
{
    int n = blockIdx.x;
    if (n >= N) return;
    int j = threadIdx.x;  // 0..127

    __shared__ float xs[32];
    if (j < 32) {
        float t = layer ? fmaxf(g_h1[n * 32 + j], 0.0f) : xin[n * 32 + j];
        xs[j] = t;
    }
    __syncthreads();

    float aq = bq[j], ak = bk[j], av = bv[j];
#pragma unroll
    for (int i = 0; i < 32; i++) {
        float xi = xs[i];
        aq = fmaf(xi, Wq[i * 128 + j], aq);
        ak = fmaf(xi, Wk[i * 128 + j], ak);
        av = fmaf(xi, Wv[i * 128 + j], av);
    }
    g_q[n * 128 + j] = aq;
    g_k[n * 128 + j] = ak;
    g_v[n * 128 + j] = av;

    if (j < 32) {
        float as = bs[j];
#pragma unroll
        for (int i = 0; i < 32; i++) as = fmaf(xs[i], Ws[i * 32 + j], as);
        float* outbuf = layer ? g_h2 : g_h1;
        outbuf[n * 32 + j] = as;
    }
}

// ---------------------------------------------------------------------------
// Edge pass A: one warp per edge.
//   e_j   = sum_i ea[i] * We[i][j]          (recomputed, We in smem)
//   alpha_h = sum_d q[dst][h,d]*(k[src][h,d]+e[h,d]) / sqrt(32)
//   expa[e,h] = exp(alpha_h)   (softmax shift-invariance: max pass skipped)
//   s[dst,h] += expa[e,h]      (atomic)
// Lane d handles column j = h*32+d for all 4 heads.
// ---------------------------------------------------------------------------
__global__ void edge_alpha_kernel(
    const int* __restrict__ ei, const float* __restrict__ ea,
    const float* __restrict__ We, int E)
{
    __shared__ float sWe[2048];  // 16 x 128
    for (int t = threadIdx.x; t < 2048; t += blockDim.x) sWe[t] = We[t];
    __syncthreads();

    int e = (int)((blockIdx.x * blockDim.x + threadIdx.x) >> 5);
    int lane = threadIdx.x & 31;
    if (e >= E) return;

    int src = ei[e];
    int dst = ei[E + e];

    float eav[16];
#pragma unroll
    for (int i = 0; i < 16; i++) eav[i] = ea[e * 16 + i];

    float acc0, acc1, acc2, acc3;
    {
        float acc[4];
#pragma unroll
        for (int h = 0; h < 4; h++) {
            int jj = h * 32 + lane;
            float ej = 0.0f;
#pragma unroll
            for (int i = 0; i < 16; i++) ej = fmaf(eav[i], sWe[i * 128 + jj], ej);
            float kj = g_k[src * 128 + jj] + ej;
            acc[h] = g_q[dst * 128 + jj] * kj;
        }
#pragma unroll
        for (int off = 16; off > 0; off >>= 1) {
#pragma unroll
            for (int h = 0; h < 4; h++)
                acc[h] += __shfl_xor_sync(0xffffffffu, acc[h], off);
        }
        acc0 = acc[0]; acc1 = acc[1]; acc2 = acc[2]; acc3 = acc[3];
    }

    if (lane < 4) {
        float r = acc0;
        if (lane == 1) r = acc1;
        else if (lane == 2) r = acc2;
        else if (lane == 3) r = acc3;
        float av = __expf(r * 0.17677669529663687f);  // * 1/sqrt(32)
        g_expa[e * 4 + lane] = av;
        atomicAdd(&g_s[dst * 4 + lane], av);
    }
}

// ---------------------------------------------------------------------------
// Edge pass B: one warp per edge.
//   a_h = expa[e,h] / (s[dst,h] + 1e-16)
//   out[dst,d] += 0.25 * sum_h a_h * (v[src][h,d] + e[h,d])   (head-collapsed:
//   only 32 atomics per edge thanks to mean over heads)
// ---------------------------------------------------------------------------
__global__ void edge_aggr_kernel(
    const int* __restrict__ ei, const float* __restrict__ ea,
    const float* __restrict__ We, int layer, int E)
{
    __shared__ float sWe[2048];
    for (int t = threadIdx.x; t < 2048; t += blockDim.x) sWe[t] = We[t];
    __syncthreads();

    int e = (int)((blockIdx.x * blockDim.x + threadIdx.x) >> 5);
    int lane = threadIdx.x & 31;
    if (e >= E) return;

    int src = ei[e];
    int dst = ei[E + e];

    float eav[16];
#pragma unroll
    for (int i = 0; i < 16; i++) eav[i] = ea[e * 16 + i];

    // lanes 0..3 compute the per-head attention weights, then broadcast
    float aa = 0.0f;
    if (lane < 4)
        aa = g_expa[e * 4 + lane] / (g_s[dst * 4 + lane] + 1e-16f);
    float a0 = __shfl_sync(0xffffffffu, aa, 0);
    float a1 = __shfl_sync(0xffffffffu, aa, 1);
    float a2 = __shfl_sync(0xffffffffu, aa, 2);
    float a3 = __shfl_sync(0xffffffffu, aa, 3);

    float contrib = 0.0f;
#pragma unroll
    for (int h = 0; h < 4; h++) {
        int jj = h * 32 + lane;
        float ej = 0.0f;
#pragma unroll
        for (int i = 0; i < 16; i++) ej = fmaf(eav[i], sWe[i * 128 + jj], ej);
        float vj = g_v[src * 128 + jj] + ej;
        float ah = (h == 0) ? a0 : (h == 1) ? a1 : (h == 2) ? a2 : a3;
        contrib = fmaf(ah, vj, contrib);
    }

    float* outbuf = layer ? g_h2 : g_h1;
    atomicAdd(&outbuf[dst * 32 + lane], 0.25f * contrib);
}

// ---------------------------------------------------------------------------
// Edge MLP: out[e] = relu([relu(h2[src]), ea, relu(h2[dst])] @ Wm1 + bm1) @ Wm2 + bm2
// One thread per edge; Wm1 (80x32), bm1, Wm2 in smem.
// ---------------------------------------------------------------------------
__global__ void edge_mlp_kernel(
    const int* __restrict__ ei, const float* __restrict__ ea,
    const float* __restrict__ Wm1, const float* __restrict__ bm1,
    const float* __restrict__ Wm2, const float* __restrict__ bm2,
    float* __restrict__ out, int E)
{
    __shared__ float sW1[80 * 32];
    __shared__ float sb1[32];
    __shared__ float sW2[32];
    for (int t = threadIdx.x; t < 2560; t += blockDim.x) sW1[t] = Wm1[t];
    if (threadIdx.x < 32) {
        sb1[threadIdx.x] = bm1[threadIdx.x];
        sW2[threadIdx.x] = Wm2[threadIdx.x];
    }
    __syncthreads();

    int e = blockIdx.x * blockDim.x + threadIdx.x;
    if (e >= E) return;

    int src = ei[e];
    int dst = ei[E + e];

    float ef[80];
#pragma unroll
    for (int i = 0; i < 32; i++) ef[i] = fmaxf(g_h2[src * 32 + i], 0.0f);
#pragma unroll
    for (int i = 0; i < 16; i++) ef[32 + i] = ea[e * 16 + i];
#pragma unroll
    for (int i = 0; i < 32; i++) ef[48 + i] = fmaxf(g_h2[dst * 32 + i], 0.0f);

    float o = bm2[0];
#pragma unroll 4
    for (int j = 0; j < 32; j++) {
        float t = sb1[j];
#pragma unroll
        for (int i = 0; i < 80; i++) t = fmaf(ef[i], sW1[i * 32 + j], t);
        o = fmaf(fmaxf(t, 0.0f), sW2[j], o);
    }
    out[e] = o;
}

// ---------------------------------------------------------------------------
extern "C" void kernel_launch(void* const* d_in, const int* in_sizes, int n_in,
                              void* d_out, int out_size)
{
    const float* x  = (const float*)d_in[0];
    const float* ea = (const float*)d_in[1];
    const int*   ei = (const int*)d_in[2];

    const float* Wq1 = (const float*)d_in[3];
    const float* bq1 = (const float*)d_in[4];
    const float* Wk1 = (const float*)d_in[5];
    const float* bk1 = (const float*)d_in[6];
    const float* Wv1 = (const float*)d_in[7];
    const float* bv1 = (const float*)d_in[8];
    const float* We1 = (const float*)d_in[9];
    const float* Ws1 = (const float*)d_in[10];
    const float* bs1 = (const float*)d_in[11];

    const float* Wq2 = (const float*)d_in[12];
    const float* bq2 = (const float*)d_in[13];
    const float* Wk2 = (const float*)d_in[14];
    const float* bk2 = (const float*)d_in[15];
    const float* Wv2 = (const float*)d_in[16];
    const float* bv2 = (const float*)d_in[17];
    const float* We2 = (const float*)d_in[18];
    const float* Ws2 = (const float*)d_in[19];
    const float* bs2 = (const float*)d_in[20];

    const float* Wm1 = (const float*)d_in[21];
    const float* bm1 = (const float*)d_in[22];
    const float* Wm2 = (const float*)d_in[23];
    const float* bm2 = (const float*)d_in[24];

    float* out = (float*)d_out;

    int N = in_sizes[0] / 32;
    int E = in_sizes[1] / 16;

    int edgeBlocks = (E + 7) / 8;        // 8 warps (edges) per 256-thread block
    int mlpBlocks  = (E + 255) / 256;
    int zeroBlocks = (N * 4 + 255) / 256;

    // ---- Layer 1 ----
    node_linear_kernel<<<N, 128>>>(x, 0, Wq1, bq1, Wk1, bk1, Wv1, bv1, Ws1, bs1, N);
    zero_s_kernel<<<zeroBlocks, 256>>>(N * 4);
    edge_alpha_kernel<<<edgeBlocks, 256>>>(ei, ea, We1, E);
    edge_aggr_kernel<<<edgeBlocks, 256>>>(ei, ea, We1, 0, E);

    // ---- Layer 2 (reads relu(g_h1)) ----
    node_linear_kernel<<<N, 128>>>(nullptr, 1, Wq2, bq2, Wk2, bk2, Wv2, bv2, Ws2, bs2, N);
    zero_s_kernel<<<zeroBlocks, 256>>>(N * 4);
    edge_alpha_kernel<<<edgeBlocks, 256>>>(ei, ea, We2, E);
    edge_aggr_kernel<<<edgeBlocks, 256>>>(ei, ea, We2, 1, E);

    // ---- Edge MLP (reads relu(g_h2)) ----
    edge_mlp_kernel<<<mlpBlocks, 256>>>(ei, ea, Wm1, bm1, Wm2, bm2, out, E);
}

// round 6
// speedup vs baseline: 1.5661x; 1.5661x over previous
#include <cuda_runtime.h>

// Problem dims (fixed by the dataset; runtime values derived from in_sizes).
#define NMAX 50000
#define EMAX 800000

// ---- scratch (device globals; no allocation allowed) ----
__device__ float g_q[NMAX * 128];
__device__ float g_k[NMAX * 128];
__device__ float g_v[NMAX * 128];
__device__ float g_G[NMAX * 64];    // G[n,h,i] = sum_d We[i,h*32+d] * q[n,h*32+d]
__device__ float g_T[NMAX * 64];    // T[n,h,i] = sum_{e->n} expa[e,h] * ea[e,i]
__device__ float g_s[NMAX * 4];     // softmax denominators
__device__ float g_h1[NMAX * 32];   // layer-1 output accumulator (skip + attention)
__device__ float g_h2[NMAX * 32];   // layer-2 output accumulator
__device__ float g_expa[EMAX * 4];  // exp(alpha) per edge per head
__device__ float g_us[NMAX * 32];   // relu(h2) @ Wm1[0:32]
__device__ float g_ud[NMAX * 32];   // relu(h2) @ Wm1[48:80]

// ---------------------------------------------------------------------------
// Zero softmax denominators (N*4) and T accumulators (N*64).
// ---------------------------------------------------------------------------
__global__ void zero_st_kernel(int N) {
    int i = blockIdx.x * blockDim.x + threadIdx.x;
    if (i < N * 4) g_s[i] = 0.0f;
    if (i < N * 64) g_T[i] = 0.0f;
}

// ---------------------------------------------------------------------------
// Node linears: q/k/v = x@W+b ([N,128]); skip = x@Ws+bs ([N,32]) into outbuf;
// also G[n, w*16+i] = sum_d We[i, w*32+d] * q[n, w*32+d]  (warp w = head).
// One block per node, 128 threads.
// ---------------------------------------------------------------------------
__global__ void node_linear_kernel(
    const float* __restrict__ xin, int layer,
    const float* __restrict__ Wq, const float* __restrict__ bq,
    const float* __restrict__ Wk, const float* __restrict__ bk,
    const float* __restrict__ Wv, const float* __restrict__ bv,
    const float* __restrict__ Ws, const float* __restrict__ bs,
    const float* __restrict__ We,
    int N)
{
    int n = blockIdx.x;
    if (n >= N) return;
    int j = threadIdx.x;  // 0..127
    int w = j >> 5;       // head
    int lane = j & 31;

    __shared__ float xs[32];
    if (j < 32) {
        float t = layer ? fmaxf(g_h1[n * 32 + j], 0.0f) : xin[n * 32 + j];
        xs[j] = t;
    }
    __syncthreads();

    float aq = bq[j], ak = bk[j], av = bv[j];
#pragma unroll
    for (int i = 0; i < 32; i++) {
        float xi = xs[i];
        aq = fmaf(xi, Wq[i * 128 + j], aq);
        ak = fmaf(xi, Wk[i * 128 + j], ak);
        av = fmaf(xi, Wv[i * 128 + j], av);
    }
    g_q[n * 128 + j] = aq;
    g_k[n * 128 + j] = ak;
    g_v[n * 128 + j] = av;

    // G[n, w*16+i] = reduce_d ( We[i*128 + j] * aq )
#pragma unroll
    for (int i = 0; i < 16; i++) {
        float t = We[i * 128 + j] * aq;
#pragma unroll
        for (int off = 16; off > 0; off >>= 1)
            t += __shfl_xor_sync(0xffffffffu, t, off);
        if (lane == 0) g_G[n * 64 + w * 16 + i] = t;
    }

    if (j < 32) {
        float as = bs[j];
#pragma unroll
        for (int i = 0; i < 32; i++) as = fmaf(xs[i], Ws[i * 32 + j], as);
        float* outbuf = layer ? g_h2 : g_h1;
        outbuf[n * 32 + j] = as;
    }
}

// ---------------------------------------------------------------------------
// Edge pass A: one warp per edge.
//   alpha_h = q[dst].k[src]|_h + sum_i ea_i * G[dst][h,i]
//   expa[e,h] = exp(alpha_h / sqrt(32))
//   s[dst,h]   += expa_h              (4 atomic lanes)
//   T[dst,h,i] += expa_h * ea_i       (64 atomic lanes, 2 REDG)
// ---------------------------------------------------------------------------
__global__ void edge_alpha_kernel(const int* __restrict__ ei,
                                  const float* __restrict__ ea, int E)
{
    int e = (int)((blockIdx.x * blockDim.x + threadIdx.x) >> 5);
    int lane = threadIdx.x & 31;
    if (e >= E) return;

    int src = ei[e];
    int dst = ei[E + e];

    float eav = (lane < 16) ? ea[e * 16 + lane] : 0.0f;

    float acc[4];
#pragma unroll
    for (int h = 0; h < 4; h++) {
        int jj = h * 32 + lane;
        acc[h] = g_q[dst * 128 + jj] * g_k[src * 128 + jj];
    }
    if (lane < 16) {
#pragma unroll
        for (int h = 0; h < 4; h++)
            acc[h] = fmaf(eav, g_G[dst * 64 + h * 16 + lane], acc[h]);
    }
#pragma unroll
    for (int off = 16; off > 0; off >>= 1) {
#pragma unroll
        for (int h = 0; h < 4; h++)
            acc[h] += __shfl_xor_sync(0xffffffffu, acc[h], off);
    }

    float av = 0.0f;
    if (lane < 4) {
        float r = acc[0];
        if (lane == 1) r = acc[1];
        else if (lane == 2) r = acc[2];
        else if (lane == 3) r = acc[3];
        av = __expf(r * 0.17677669529663687f);  // 1/sqrt(32)
        g_expa[e * 4 + lane] = av;
        atomicAdd(&g_s[dst * 4 + lane], av);
    }
    float e0 = __shfl_sync(0xffffffffu, av, 0);
    float e1 = __shfl_sync(0xffffffffu, av, 1);
    float e2 = __shfl_sync(0xffffffffu, av, 2);
    float e3 = __shfl_sync(0xffffffffu, av, 3);

    // T accumulation: lane -> (h, i). Two REDGs cover h={0,1} and h={2,3}.
    int i = lane & 15;
    int hb = lane >> 4;  // 0 or 1
    float eai = __shfl_sync(0xffffffffu, eav, i);
    float v01 = ((hb == 0) ? e0 : e1) * eai;
    atomicAdd(&g_T[dst * 64 + hb * 16 + i], v01);
    float v23 = ((hb == 0) ? e2 : e3) * eai;
    atomicAdd(&g_T[dst * 64 + (2 + hb) * 16 + i], v23);
}

// ---------------------------------------------------------------------------
// Edge pass B: one warp per edge. Only the v-gather part (e-part via T).
//   a_h = expa[e,h] / (s[dst,h] + 1e-16)
//   out[dst,d] += 0.25 * sum_h a_h * v[src][h,d]
// ---------------------------------------------------------------------------
__global__ void edge_aggr_kernel(const int* __restrict__ ei, int layer, int E)
{
    int e = (int)((blockIdx.x * blockDim.x + threadIdx.x) >> 5);
    int lane = threadIdx.x & 31;
    if (e >= E) return;

    int src = ei[e];
    int dst = ei[E + e];

    float aa = 0.0f;
    if (lane < 4)
        aa = g_expa[e * 4 + lane] / (g_s[dst * 4 + lane] + 1e-16f);
    float a0 = __shfl_sync(0xffffffffu, aa, 0);
    float a1 = __shfl_sync(0xffffffffu, aa, 1);
    float a2 = __shfl_sync(0xffffffffu, aa, 2);
    float a3 = __shfl_sync(0xffffffffu, aa, 3);

    const float* vrow = &g_v[src * 128];
    float contrib;
    contrib = a0 * vrow[lane];
    contrib = fmaf(a1, vrow[32 + lane], contrib);
    contrib = fmaf(a2, vrow[64 + lane], contrib);
    contrib = fmaf(a3, vrow[96 + lane], contrib);

    float* outbuf = layer ? g_h2 : g_h1;
    atomicAdd(&outbuf[dst * 32 + lane], 0.25f * contrib);
}

// ---------------------------------------------------------------------------
// Finalize: add the e-part of the aggregation, per node:
//   out[n,d] += 0.25 * sum_h (1/(s_h+1e-16)) * sum_i We[i,h*32+d] * T[n,h,i]
// One warp per node.
// ---------------------------------------------------------------------------
__global__ void finalize_kernel(const float* __restrict__ We, int layer, int N)
{
    __shared__ float sWe[2048];  // 16 x 128
    for (int t = threadIdx.x; t < 2048; t += blockDim.x) sWe[t] = We[t];
    __syncthreads();

    int n = (int)((blockIdx.x * blockDim.x + threadIdx.x) >> 5);
    int lane = threadIdx.x & 31;
    if (n >= N) return;

    float sv = 0.0f;
    if (lane < 4) sv = 1.0f / (g_s[n * 4 + lane] + 1e-16f);
    float inv0 = __shfl_sync(0xffffffffu, sv, 0);
    float inv1 = __shfl_sync(0xffffffffu, sv, 1);
    float inv2 = __shfl_sync(0xffffffffu, sv, 2);
    float inv3 = __shfl_sync(0xffffffffu, sv, 3);

    float Tv0 = g_T[n * 64 + lane];        // covers (h,i) for h=0,1
    float Tv1 = g_T[n * 64 + 32 + lane];   // covers (h,i) for h=2,3

    float add = 0.0f;
#pragma unroll
    for (int h = 0; h < 4; h++) {
        float acc = 0.0f;
#pragma unroll
        for (int i = 0; i < 16; i++) {
            float t = (h < 2) ? __shfl_sync(0xffffffffu, Tv0, h * 16 + i)
                              : __shfl_sync(0xffffffffu, Tv1, (h - 2) * 16 + i);
            acc = fmaf(sWe[i * 128 + h * 32 + lane], t, acc);
        }
        float inv = (h == 0) ? inv0 : (h == 1) ? inv1 : (h == 2) ? inv2 : inv3;
        add = fmaf(inv, acc, add);
    }

    float* outbuf = layer ? g_h2 : g_h1;
    outbuf[n * 32 + lane] += 0.25f * add;
}

// ---------------------------------------------------------------------------
// MLP node precompute: u_src = relu(h2)@Wm1[0:32], u_dst = relu(h2)@Wm1[48:80]
// One warp per node.
// ---------------------------------------------------------------------------
__global__ void mlp_pre_kernel(const float* __restrict__ Wm1, int N)
{
    __shared__ float sWa[1024];  // Wm1 rows 0..31
    __shared__ float sWc[1024];  // Wm1 rows 48..79
    for (int t = threadIdx.x; t < 1024; t += blockDim.x) {
        sWa[t] = Wm1[t];
        sWc[t] = Wm1[1536 + t];
    }
    __syncthreads();

    int n = (int)((blockIdx.x * blockDim.x + threadIdx.x) >> 5);
    int lane = threadIdx.x & 31;
    if (n >= N) return;

    float r = fmaxf(g_h2[n * 32 + lane], 0.0f);
    float us = 0.0f, ud = 0.0f;
#pragma unroll
    for (int i = 0; i < 32; i++) {
        float xi = __shfl_sync(0xffffffffu, r, i);
        us = fmaf(xi, sWa[i * 32 + lane], us);
        ud = fmaf(xi, sWc[i * 32 + lane], ud);
    }
    g_us[n * 32 + lane] = us;
    g_ud[n * 32 + lane] = ud;
}

// ---------------------------------------------------------------------------
// Edge MLP: one warp per edge.
//   t_j = us[src][j] + ud[dst][j] + sum_i ea_i*Wm1[32+i][j] + b1_j
//   out[e] = sum_j relu(t_j)*W2_j + b2
// ---------------------------------------------------------------------------
__global__ void edge_mlp_kernel(
    const int* __restrict__ ei, const float* __restrict__ ea,
    const float* __restrict__ Wm1, const float* __restrict__ bm1,
    const float* __restrict__ Wm2, const float* __restrict__ bm2,
    float* __restrict__ out, int E)
{
    __shared__ float sWe2[512];  // Wm1 rows 32..47
    __shared__ float sb1[32];
    __shared__ float sW2[32];
    for (int t = threadIdx.x; t < 512; t += blockDim.x) sWe2[t] = Wm1[1024 + t];
    if (threadIdx.x < 32) {
        sb1[threadIdx.x] = bm1[threadIdx.x];
        sW2[threadIdx.x] = Wm2[threadIdx.x];
    }
    __syncthreads();

    int e = (int)((blockIdx.x * blockDim.x + threadIdx.x) >> 5);
    int lane = threadIdx.x & 31;
    if (e >= E) return;

    int src = ei[e];
    int dst = ei[E + e];

    float eav = (lane < 16) ? ea[e * 16 + lane] : 0.0f;

    float t = g_us[src * 32 + lane] + g_ud[dst * 32 + lane] + sb1[lane];
#pragma unroll
    for (int i = 0; i < 16; i++) {
        float xi = __shfl_sync(0xffffffffu, eav, i);
        t = fmaf(xi, sWe2[i * 32 + lane], t);
    }
    float o = fmaxf(t, 0.0f) * sW2[lane];
#pragma unroll
    for (int off = 16; off > 0; off >>= 1)
        o += __shfl_xor_sync(0xffffffffu, o, off);
    if (lane == 0) out[e] = o + bm2[0];
}

// ---------------------------------------------------------------------------
extern "C" void kernel_launch(void* const* d_in, const int* in_sizes, int n_in,
                              void* d_out, int out_size)
{
    const float* x  = (const float*)d_in[0];
    const float* ea = (const float*)d_in[1];
    const int*   ei = (const int*)d_in[2];

    const float* Wq1 = (const float*)d_in[3];
    const float* bq1 = (const float*)d_in[4];
    const float* Wk1 = (const float*)d_in[5];
    const float* bk1 = (const float*)d_in[6];
    const float* Wv1 = (const float*)d_in[7];
    const float* bv1 = (const float*)d_in[8];
    const float* We1 = (const float*)d_in[9];
    const float* Ws1 = (const float*)d_in[10];
    const float* bs1 = (const float*)d_in[11];

    const float* Wq2 = (const float*)d_in[12];
    const float* bq2 = (const float*)d_in[13];
    const float* Wk2 = (const float*)d_in[14];
    const float* bk2 = (const float*)d_in[15];
    const float* Wv2 = (const float*)d_in[16];
    const float* bv2 = (const float*)d_in[17];
    const float* We2 = (const float*)d_in[18];
    const float* Ws2 = (const float*)d_in[19];
    const float* bs2 = (const float*)d_in[20];

    const float* Wm1 = (const float*)d_in[21];
    const float* bm1 = (const float*)d_in[22];
    const float* Wm2 = (const float*)d_in[23];
    const float* bm2 = (const float*)d_in[24];

    float* out = (float*)d_out;

    int N = in_sizes[0] / 32;
    int E = in_sizes[1] / 16;

    int edgeBlocks = (E + 7) / 8;              // warp per edge, 256-thread blocks
    int nodeWarpBlocks = (N + 7) / 8;          // warp per node, 256-thread blocks
    int zeroBlocks = (N * 64 + 255) / 256;

    // ---- Layer 1 ----
    node_linear_kernel<<<N, 128>>>(x, 0, Wq1, bq1, Wk1, bk1, Wv1, bv1, Ws1, bs1, We1, N);
    zero_st_kernel<<<zeroBlocks, 256>>>(N);
    edge_alpha_kernel<<<edgeBlocks, 256>>>(ei, ea, E);
    edge_aggr_kernel<<<edgeBlocks, 256>>>(ei, 0, E);
    finalize_kernel<<<nodeWarpBlocks, 256>>>(We1, 0, N);

    // ---- Layer 2 (reads relu(g_h1)) ----
    node_linear_kernel<<<N, 128>>>(nullptr, 1, Wq2, bq2, Wk2, bk2, Wv2, bv2, Ws2, bs2, We2, N);
    zero_st_kernel<<<zeroBlocks, 256>>>(N);
    edge_alpha_kernel<<<edgeBlocks, 256>>>(ei, ea, E);
    edge_aggr_kernel<<<edgeBlocks, 256>>>(ei, 1, E);
    finalize_kernel<<<nodeWarpBlocks, 256>>>(We2, 1, N);

    // ---- Edge MLP ----
    mlp_pre_kernel<<<nodeWarpBlocks, 256>>>(Wm1, N);
    edge_mlp_kernel<<<edgeBlocks, 256>>>(ei, ea, Wm1, bm1, Wm2, bm2, out, E);
}

// round 7
// speedup vs baseline: 1.9773x; 1.2626x over previous
#include <cuda_runtime.h>

// Problem dims (fixed by the dataset; runtime values derived from in_sizes).
#define NMAX 50000
#define EMAX 800000

// ---- scratch (device globals; no allocation allowed) ----
__device__ float g_q[NMAX * 128];
__device__ float g_k[NMAX * 128];
__device__ float g_v[NMAX * 128];
__device__ float g_G[NMAX * 64];    // G[n,h*16+i] = sum_d We[i,h*32+d] * q[n,h*32+d]
__device__ float g_h1[NMAX * 32];   // layer-1 output (skip + attention)
__device__ float g_h2[NMAX * 32];   // layer-2 output
__device__ float g_us[NMAX * 32];   // relu(h2) @ Wm1[0:32]
__device__ float g_ud[NMAX * 32];   // relu(h2) @ Wm1[48:80]

// ---- CSR (dst-sorted edges), built once per launch ----
__device__ int g_deg[NMAX];
__device__ int g_rowptr[NMAX + 1];
__device__ int g_cursor[NMAX];
__device__ int g_srcsorted[EMAX];
__device__ int g_eidsorted[EMAX];
__device__ int g_blocksums[256];    // (NMAX+255)/256 = 196 <= 256

// ===========================================================================
// CSR build: zero -> histogram -> 3-phase scan -> scatter
// ===========================================================================
__global__ void csr_zero_kernel(int N) {
    int i = blockIdx.x * blockDim.x + threadIdx.x;
    if (i < N) g_deg[i] = 0;
}

__global__ void csr_hist_kernel(const int* __restrict__ ei, int E) {
    int e = blockIdx.x * blockDim.x + threadIdx.x;
    if (e < E) atomicAdd(&g_deg[ei[E + e]], 1);
}

__global__ void csr_scan1_kernel(int N) {
    __shared__ int sh[256];
    int tid = threadIdx.x;
    int i = blockIdx.x * 256 + tid;
    int v = (i < N) ? g_deg[i] : 0;
    sh[tid] = v;
    __syncthreads();
#pragma unroll
    for (int off = 1; off < 256; off <<= 1) {
        int t = (tid >= off) ? sh[tid - off] : 0;
        __syncthreads();
        sh[tid] += t;
        __syncthreads();
    }
    if (i < N) g_rowptr[i + 1] = sh[tid];   // local inclusive, fixed in scan3
    if (tid == 255) g_blocksums[blockIdx.x] = sh[255];
}

__global__ void csr_scan2_kernel(int nb) {
    __shared__ int sh[256];
    int tid = threadIdx.x;
    int orig = (tid < nb) ? g_blocksums[tid] : 0;
    sh[tid] = orig;
    __syncthreads();
#pragma unroll
    for (int off = 1; off < 256; off <<= 1) {
        int t = (tid >= off) ? sh[tid - off] : 0;
        __syncthreads();
        sh[tid] += t;
        __syncthreads();
    }
    if (tid < nb) g_blocksums[tid] = sh[tid] - orig;  // exclusive
}

__global__ void csr_scan3_kernel(int N) {
    int i = blockIdx.x * blockDim.x + threadIdx.x;
    if (i < N) {
        int off = g_blocksums[i >> 8];
        int incl = g_rowptr[i + 1] + off;
        g_rowptr[i + 1] = incl;
        g_cursor[i] = incl - g_deg[i];
    }
    if (i == 0) g_rowptr[0] = 0;
}

__global__ void csr_scatter_kernel(const int* __restrict__ ei, int E) {
    int e = blockIdx.x * blockDim.x + threadIdx.x;
    if (e >= E) return;
    int src = ei[e];
    int dst = ei[E + e];
    int p = atomicAdd(&g_cursor[dst], 1);
    g_srcsorted[p] = src;
    g_eidsorted[p] = e;
}

// ===========================================================================
// Node linears: q/k/v = x@W+b ([N,128]); skip = x@Ws+bs ([N,32]) into outbuf;
// G[n, w*16+i] = sum_d We[i, w*32+d] * q[n, w*32+d]  (warp w = head).
// One block per node, 128 threads.
// ===========================================================================
__global__ void node_linear_kernel(
    const float* __restrict__ xin, int layer,
    const float* __restrict__ Wq, const float* __restrict__ bq,
    const float* __restrict__ Wk, const float* __restrict__ bk,
    const float* __restrict__ Wv, const float* __restrict__ bv,
    const float* __restrict__ Ws, const float* __restrict__ bs,
    const float* __restrict__ We,
    int N)
{
    int n = blockIdx.x;
    if (n >= N) return;
    int j = threadIdx.x;  // 0..127
    int w = j >> 5;       // head
    int lane = j & 31;

    __shared__ float xs[32];
    if (j < 32) {
        float t = layer ? fmaxf(g_h1[n * 32 + j], 0.0f) : xin[n * 32 + j];
        xs[j] = t;
    }
    __syncthreads();

    float aq = bq[j], ak = bk[j], av = bv[j];
#pragma unroll
    for (int i = 0; i < 32; i++) {
        float xi = xs[i];
        aq = fmaf(xi, Wq[i * 128 + j], aq);
        ak = fmaf(xi, Wk[i * 128 + j], ak);
        av = fmaf(xi, Wv[i * 128 + j], av);
    }
    g_q[n * 128 + j] = aq;
    g_k[n * 128 + j] = ak;
    g_v[n * 128 + j] = av;

#pragma unroll
    for (int i = 0; i < 16; i++) {
        float t = We[i * 128 + j] * aq;
#pragma unroll
        for (int off = 16; off > 0; off >>= 1)
            t += __shfl_xor_sync(0xffffffffu, t, off);
        if (lane == 0) g_G[n * 64 + w * 16 + i] = t;
    }

    if (j < 32) {
        float as = bs[j];
#pragma unroll
        for (int i = 0; i < 32; i++) as = fmaf(xs[i], Ws[i * 32 + j], as);
        float* outbuf = layer ? g_h2 : g_h1;
        outbuf[n * 32 + j] = as;
    }
}

// ===========================================================================
// Fused per-node attention: one warp per node, CSR over incoming edges.
// Register accumulation only — NO atomics.
//   alpha_h = q[n].k[src]|_h + sum_i ea_i*G[n,h,i]
//   exph    = exp(alpha_h/sqrt(32))
//   s_h    += exph ; O_h[d] += exph*v[src][h,d] ; T[h,i] += exph*ea_i
// tail: out[n,d] += 0.25*( sum_h O_h[d]/s_h + sum_h (1/s_h) sum_i We[i,h,d]T[h,i] )
// ===========================================================================
__global__ void node_attn_kernel(const float* __restrict__ ea,
                                 const float* __restrict__ We,
                                 int layer, int N)
{
    __shared__ float sWe[2048];  // 16 x 128
    for (int t = threadIdx.x; t < 2048; t += blockDim.x) sWe[t] = We[t];
    __syncthreads();

    int n = (int)((blockIdx.x * blockDim.x + threadIdx.x) >> 5);
    int lane = threadIdx.x & 31;
    if (n >= N) return;

    int rs = g_rowptr[n];
    int re = g_rowptr[n + 1];

    // per-node loads (once)
    float q0 = g_q[n * 128 + lane];
    float q1 = g_q[n * 128 + 32 + lane];
    float q2 = g_q[n * 128 + 64 + lane];
    float q3 = g_q[n * 128 + 96 + lane];
    float G0 = (lane < 16) ? g_G[n * 64 + lane] : 0.0f;
    float G1 = (lane < 16) ? g_G[n * 64 + 16 + lane] : 0.0f;
    float G2 = (lane < 16) ? g_G[n * 64 + 32 + lane] : 0.0f;
    float G3 = (lane < 16) ? g_G[n * 64 + 48 + lane] : 0.0f;

    float accO0 = 0.0f, accO1 = 0.0f, accO2 = 0.0f, accO3 = 0.0f;
    float accT0 = 0.0f, accT1 = 0.0f;   // T[(lane>>4),i] and T[2+(lane>>4),i]
    float accS = 0.0f;                  // lanes 0..3 hold s_h
    int hb = lane >> 4;
    int ii = lane & 15;

    for (int p = rs; p < re; p++) {
        int src = g_srcsorted[p];
        int eid = g_eidsorted[p];
        float eav = (lane < 16) ? ea[(size_t)eid * 16 + lane] : 0.0f;

        const float* krow = &g_k[src * 128];
        float a0 = q0 * krow[lane]      + eav * G0;
        float a1 = q1 * krow[32 + lane] + eav * G1;
        float a2 = q2 * krow[64 + lane] + eav * G2;
        float a3 = q3 * krow[96 + lane] + eav * G3;
#pragma unroll
        for (int off = 16; off > 0; off >>= 1) {
            a0 += __shfl_xor_sync(0xffffffffu, a0, off);
            a1 += __shfl_xor_sync(0xffffffffu, a1, off);
            a2 += __shfl_xor_sync(0xffffffffu, a2, off);
            a3 += __shfl_xor_sync(0xffffffffu, a3, off);
        }

        float av = 0.0f;
        if (lane < 4) {
            float r = a0;
            if (lane == 1) r = a1;
            else if (lane == 2) r = a2;
            else if (lane == 3) r = a3;
            av = __expf(r * 0.17677669529663687f);  // 1/sqrt(32)
            accS += av;
        }
        float e0 = __shfl_sync(0xffffffffu, av, 0);
        float e1 = __shfl_sync(0xffffffffu, av, 1);
        float e2 = __shfl_sync(0xffffffffu, av, 2);
        float e3 = __shfl_sync(0xffffffffu, av, 3);

        const float* vrow = &g_v[src * 128];
        accO0 = fmaf(e0, vrow[lane],      accO0);
        accO1 = fmaf(e1, vrow[32 + lane], accO1);
        accO2 = fmaf(e2, vrow[64 + lane], accO2);
        accO3 = fmaf(e3, vrow[96 + lane], accO3);

        float eai = __shfl_sync(0xffffffffu, eav, ii);
        accT0 = fmaf((hb == 0) ? e0 : e1, eai, accT0);
        accT1 = fmaf((hb == 0) ? e2 : e3, eai, accT1);
    }

    // inverse denominators
    float sv = 0.0f;
    if (lane < 4) sv = 1.0f / (accS + 1e-16f);
    float inv0 = __shfl_sync(0xffffffffu, sv, 0);
    float inv1 = __shfl_sync(0xffffffffu, sv, 1);
    float inv2 = __shfl_sync(0xffffffffu, sv, 2);
    float inv3 = __shfl_sync(0xffffffffu, sv, 3);

    // v-part
    float res = inv0 * accO0;
    res = fmaf(inv1, accO1, res);
    res = fmaf(inv2, accO2, res);
    res = fmaf(inv3, accO3, res);

    // e-part: sum_h inv_h * sum_i We[i, h*32+lane] * T[h,i]
#pragma unroll
    for (int h = 0; h < 4; h++) {
        float acc = 0.0f;
#pragma unroll
        for (int i = 0; i < 16; i++) {
            float t = (h < 2) ? __shfl_sync(0xffffffffu, accT0, h * 16 + i)
                              : __shfl_sync(0xffffffffu, accT1, (h - 2) * 16 + i);
            acc = fmaf(sWe[i * 128 + h * 32 + lane], t, acc);
        }
        float inv = (h == 0) ? inv0 : (h == 1) ? inv1 : (h == 2) ? inv2 : inv3;
        res = fmaf(inv, acc, res);
    }

    float* outbuf = layer ? g_h2 : g_h1;
    outbuf[n * 32 + lane] += 0.25f * res;   // skip already there; no atomics
}

// ===========================================================================
// MLP node precompute: u_src = relu(h2)@Wm1[0:32], u_dst = relu(h2)@Wm1[48:80]
// ===========================================================================
__global__ void mlp_pre_kernel(const float* __restrict__ Wm1, int N)
{
    __shared__ float sWa[1024];
    __shared__ float sWc[1024];
    for (int t = threadIdx.x; t < 1024; t += blockDim.x) {
        sWa[t] = Wm1[t];
        sWc[t] = Wm1[1536 + t];
    }
    __syncthreads();

    int n = (int)((blockIdx.x * blockDim.x + threadIdx.x) >> 5);
    int lane = threadIdx.x & 31;
    if (n >= N) return;

    float r = fmaxf(g_h2[n * 32 + lane], 0.0f);
    float us = 0.0f, ud = 0.0f;
#pragma unroll
    for (int i = 0; i < 32; i++) {
        float xi = __shfl_sync(0xffffffffu, r, i);
        us = fmaf(xi, sWa[i * 32 + lane], us);
        ud = fmaf(xi, sWc[i * 32 + lane], ud);
    }
    g_us[n * 32 + lane] = us;
    g_ud[n * 32 + lane] = ud;
}

// ===========================================================================
// Edge MLP: one warp per edge.
// ===========================================================================
__global__ void edge_mlp_kernel(
    const int* __restrict__ ei, const float* __restrict__ ea,
    const float* __restrict__ Wm1, const float* __restrict__ bm1,
    const float* __restrict__ Wm2, const float* __restrict__ bm2,
    float* __restrict__ out, int E)
{
    __shared__ float sWe2[512];
    __shared__ float sb1[32];
    __shared__ float sW2[32];
    for (int t = threadIdx.x; t < 512; t += blockDim.x) sWe2[t] = Wm1[1024 + t];
    if (threadIdx.x < 32) {
        sb1[threadIdx.x] = bm1[threadIdx.x];
        sW2[threadIdx.x] = Wm2[threadIdx.x];
    }
    __syncthreads();

    int e = (int)((blockIdx.x * blockDim.x + threadIdx.x) >> 5);
    int lane = threadIdx.x & 31;
    if (e >= E) return;

    int src = ei[e];
    int dst = ei[E + e];

    float eav = (lane < 16) ? ea[(size_t)e * 16 + lane] : 0.0f;

    float t = g_us[src * 32 + lane] + g_ud[dst * 32 + lane] + sb1[lane];
#pragma unroll
    for (int i = 0; i < 16; i++) {
        float xi = __shfl_sync(0xffffffffu, eav, i);
        t = fmaf(xi, sWe2[i * 32 + lane], t);
    }
    float o = fmaxf(t, 0.0f) * sW2[lane];
#pragma unroll
    for (int off = 16; off > 0; off >>= 1)
        o += __shfl_xor_sync(0xffffffffu, o, off);
    if (lane == 0) out[e] = o + bm2[0];
}

// ===========================================================================
extern "C" void kernel_launch(void* const* d_in, const int* in_sizes, int n_in,
                              void* d_out, int out_size)
{
    const float* x  = (const float*)d_in[0];
    const float* ea = (const float*)d_in[1];
    const int*   ei = (const int*)d_in[2];

    const float* Wq1 = (const float*)d_in[3];
    const float* bq1 = (const float*)d_in[4];
    const float* Wk1 = (const float*)d_in[5];
    const float* bk1 = (const float*)d_in[6];
    const float* Wv1 = (const float*)d_in[7];
    const float* bv1 = (const float*)d_in[8];
    const float* We1 = (const float*)d_in[9];
    const float* Ws1 = (const float*)d_in[10];
    const float* bs1 = (const float*)d_in[11];

    const float* Wq2 = (const float*)d_in[12];
    const float* bq2 = (const float*)d_in[13];
    const float* Wk2 = (const float*)d_in[14];
    const float* bk2 = (const float*)d_in[15];
    const float* Wv2 = (const float*)d_in[16];
    const float* bv2 = (const float*)d_in[17];
    const float* We2 = (const float*)d_in[18];
    const float* Ws2 = (const float*)d_in[19];
    const float* bs2 = (const float*)d_in[20];

    const float* Wm1 = (const float*)d_in[21];
    const float* bm1 = (const float*)d_in[22];
    const float* Wm2 = (const float*)d_in[23];
    const float* bm2 = (const float*)d_in[24];

    float* out = (float*)d_out;

    int N = in_sizes[0] / 32;
    int E = in_sizes[1] / 16;

    int nBlocks256  = (N + 255) / 256;
    int eBlocks256  = (E + 255) / 256;
    int edgeWarpBlocks = (E + 7) / 8;
    int nodeWarpBlocks = (N + 7) / 8;
    int nbScan = (N + 255) / 256;

    // ---- CSR build (shared by both layers) ----
    csr_zero_kernel<<<nBlocks256, 256>>>(N);
    csr_hist_kernel<<<eBlocks256, 256>>>(ei, E);
    csr_scan1_kernel<<<nbScan, 256>>>(N);
    csr_scan2_kernel<<<1, 256>>>(nbScan);
    csr_scan3_kernel<<<nBlocks256, 256>>>(N);
    csr_scatter_kernel<<<eBlocks256, 256>>>(ei, E);

    // ---- Layer 1 ----
    node_linear_kernel<<<N, 128>>>(x, 0, Wq1, bq1, Wk1, bk1, Wv1, bv1, Ws1, bs1, We1, N);
    node_attn_kernel<<<nodeWarpBlocks, 256>>>(ea, We1, 0, N);

    // ---- Layer 2 ----
    node_linear_kernel<<<N, 128>>>(nullptr, 1, Wq2, bq2, Wk2, bk2, Wv2, bv2, Ws2, bs2, We2, N);
    node_attn_kernel<<<nodeWarpBlocks, 256>>>(ea, We2, 1, N);

    // ---- Edge MLP ----
    mlp_pre_kernel<<<nodeWarpBlocks, 256>>>(Wm1, N);
    edge_mlp_kernel<<<edgeWarpBlocks, 256>>>(ei, ea, Wm1, bm1, Wm2, bm2, out, E);
}